// round 1
// baseline (speedup 1.0000x reference)
#include <cuda_runtime.h>
#include <cuda_bf16.h>
#include <math_constants.h>

// Problem constants (fixed by setup_inputs)
#define NPTS  16384
#define BATCH 8
#define M     2048
#define CH    128

// smem layout: per-batch stride padded by 1 float so different batches hit
// different banks (6145 mod 32 == 1)
#define SMEM_STRIDE 6145
#define SMEM_FLOATS (BATCH * SMEM_STRIDE)     // 49160 floats
#define SMEM_BYTES  (SMEM_FLOATS * 4)         // 196,640 B

#define NBLOCKS 128
#define NTHREADS 1024
#define NWARPS_TOTAL (NBLOCKS * (NTHREADS / 32))   // 4096 -> 4 points per warp

// Scratch: transposed features [B][m][C]
__device__ float g_featsT[BATCH * M * CH];

// ---------------------------------------------------------------------------
// Kernel A: transpose known_feats (B, C, m) -> g_featsT (B, m, C)
// ---------------------------------------------------------------------------
__global__ void transpose_feats_kernel(const float* __restrict__ in)
{
    __shared__ float tile[32][33];
    const int b  = blockIdx.z;
    const int j0 = blockIdx.x * 32;   // m dimension
    const int c0 = blockIdx.y * 32;   // channel dimension
    const int tx = threadIdx.x;
    const int ty = threadIdx.y;

    #pragma unroll
    for (int i = ty; i < 32; i += 8)
        tile[i][tx] = in[((size_t)(b * CH + c0 + i)) * M + j0 + tx];
    __syncthreads();
    #pragma unroll
    for (int i = ty; i < 32; i += 8)
        g_featsT[((size_t)(b * M + j0 + i)) * CH + c0 + tx] = tile[tx][i];
}

// ---------------------------------------------------------------------------
// Kernel B: one warp per query point.
//   - all 8 batches of known coords staged in smem (bank-padded)
//   - lanes stride the 2048 candidates (64 iters), local top-3 per lane
//   - warp merge of top-3 via 64-bit keys (d2 bits << 32 | idx): the uint
//     ordering of non-negative floats is monotone, and ties prefer lower idx
//     (matches jax top_k tie-break)
//   - feature combine: lane l handles channels [4l, 4l+4) as float4
// ---------------------------------------------------------------------------
__global__ void __launch_bounds__(NTHREADS, 1)
knn_interp_kernel(const float* __restrict__ unknown,
                  const float* __restrict__ known,
                  const int* __restrict__ batch_inds,
                  float* __restrict__ out)
{
    extern __shared__ float sk[];
    const int tid = threadIdx.x;

    // cooperative fill of smem coords (coalesced global reads)
    for (int i = tid; i < BATCH * M * 3; i += NTHREADS) {
        int b = i / (M * 3);
        int r = i - b * (M * 3);
        sk[b * SMEM_STRIDE + r] = known[i];
    }
    __syncthreads();

    const int lane = tid & 31;
    const int gw   = blockIdx.x * (NTHREADS / 32) + (tid >> 5);

    for (int p = gw; p < NPTS; p += NWARPS_TOTAL) {
        const float ux = unknown[p * 3 + 0];
        const float uy = unknown[p * 3 + 1];
        const float uz = unknown[p * 3 + 2];
        const int   b  = batch_inds[p];
        const float* kb = sk + b * SMEM_STRIDE;

        float d0 = CUDART_INF_F, d1 = CUDART_INF_F, d2 = CUDART_INF_F;
        int   i0 = 0, i1 = 0, i2 = 0;

        #pragma unroll 4
        for (int j = lane; j < M; j += 32) {
            float dx = kb[3 * j + 0] - ux;
            float dy = kb[3 * j + 1] - uy;
            float dz = kb[3 * j + 2] - uz;
            float d  = fmaf(dx, dx, fmaf(dy, dy, dz * dz));
            if (d < d2) {
                if (d < d1) {
                    d2 = d1; i2 = i1;
                    if (d < d0) { d1 = d0; i1 = i0; d0 = d; i0 = j; }
                    else        { d1 = d;  i1 = j; }
                } else { d2 = d; i2 = j; }
            }
        }

        // local sorted keys
        unsigned long long kl0 = ((unsigned long long)__float_as_uint(d0) << 32) | (unsigned)i0;
        unsigned long long kl1 = ((unsigned long long)__float_as_uint(d1) << 32) | (unsigned)i1;
        unsigned long long kl2 = ((unsigned long long)__float_as_uint(d2) << 32) | (unsigned)i2;

        float wd[3]; int wi[3];
        int r = 0;
        #pragma unroll
        for (int s = 0; s < 3; s++) {
            unsigned long long v =
                (r == 0) ? kl0 : (r == 1) ? kl1 : (r == 2) ? kl2
                                                           : 0xFFFFFFFFFFFFFFFFull;
            unsigned long long mine = v;
            #pragma unroll
            for (int off = 16; off; off >>= 1) {
                unsigned long long o = __shfl_xor_sync(0xffffffffu, v, off);
                v = (o < v) ? o : v;
            }
            if (r < 3 && v == mine) r++;
            wd[s] = __uint_as_float((unsigned)(v >> 32));
            wi[s] = (int)(unsigned)(v & 0xffffffffu);
        }

        // weights
        float w0 = 1.0f / (sqrtf(wd[0]) + 1e-8f);
        float w1 = 1.0f / (sqrtf(wd[1]) + 1e-8f);
        float w2 = 1.0f / (sqrtf(wd[2]) + 1e-8f);
        float inv = 1.0f / (w0 + w1 + w2);
        w0 *= inv; w1 *= inv; w2 *= inv;

        // gather + combine: rows are contiguous 512B in g_featsT
        const float4* f0 = (const float4*)(g_featsT + ((size_t)(b * M + wi[0])) * CH);
        const float4* f1 = (const float4*)(g_featsT + ((size_t)(b * M + wi[1])) * CH);
        const float4* f2 = (const float4*)(g_featsT + ((size_t)(b * M + wi[2])) * CH);

        float4 a0 = f0[lane], a1 = f1[lane], a2 = f2[lane];
        float4 o;
        o.x = fmaf(w0, a0.x, fmaf(w1, a1.x, w2 * a2.x));
        o.y = fmaf(w0, a0.y, fmaf(w1, a1.y, w2 * a2.y));
        o.z = fmaf(w0, a0.z, fmaf(w1, a1.z, w2 * a2.z));
        o.w = fmaf(w0, a0.w, fmaf(w1, a1.w, w2 * a2.w));
        ((float4*)out)[(size_t)p * (CH / 4) + lane] = o;
    }
}

// ---------------------------------------------------------------------------
extern "C" void kernel_launch(void* const* d_in, const int* in_sizes, int n_in,
                              void* d_out, int out_size)
{
    const float* unknown     = (const float*)d_in[0];
    const float* known       = (const float*)d_in[1];
    const int*   batch_inds  = (const int*)d_in[2];
    const float* known_feats = (const float*)d_in[3];
    float* out = (float*)d_out;

    // allow >48KB dynamic smem (idempotent, host-side attribute)
    static bool attr_set = false;
    if (!attr_set) {
        cudaFuncSetAttribute(knn_interp_kernel,
                             cudaFuncAttributeMaxDynamicSharedMemorySize,
                             SMEM_BYTES);
        attr_set = true;
    }

    transpose_feats_kernel<<<dim3(M / 32, CH / 32, BATCH), dim3(32, 8)>>>(known_feats);
    knn_interp_kernel<<<NBLOCKS, NTHREADS, SMEM_BYTES>>>(unknown, known, batch_inds, out);
}